// round 4
// baseline (speedup 1.0000x reference)
#include <cuda_runtime.h>
#include <cuda_bf16.h>

#define KEHALF_F 7.199822675975274f
#define MAX_ATOMS 500000
#define MAXZ 96
#define LOG2E_F 1.4426950408889634f

struct ZConsts {
    float spadiv;               // sp(adiv)
    float ns1, ns2, ns3, ns4;   // -sp(a_k) * log2(e)
    float c1n, c2n, c3n, c4n;   // KEHALF * sp(c_k)/csum
};

__device__ ZConsts g_consts;
__device__ float g_lut[MAXZ];            // k^sp(apow)
__device__ unsigned char g_zq[MAX_ATOMS];

__device__ __forceinline__ float softplus_acc(float x) {
    return (x > 20.f) ? x : log1pf(expf(x));
}

// One kernel: quantize Zf to bytes, zero the output, and (block 0) compute
// the scalar constants + the 95-entry z LUT.
__global__ void __launch_bounds__(256)
atom_kernel(const float* __restrict__ Zf, float* __restrict__ out, int n,
            const float* adiv, const float* apow,
            const float* c1, const float* c2, const float* c3, const float* c4,
            const float* a1, const float* a2, const float* a3, const float* a4) {
    int i = blockIdx.x * blockDim.x + threadIdx.x;
    if (i < n) {
        g_zq[i] = (unsigned char)__float2int_rn(Zf[i]);
        out[i] = 0.0f;
    }
    if (blockIdx.x == 0) {
        if (threadIdx.x < MAXZ) {
            float sp_apow = softplus_acc(*apow);
            g_lut[threadIdx.x] = powf((float)threadIdx.x, sp_apow);
        }
        if (threadIdx.x == 0) {
            ZConsts C;
            C.spadiv = softplus_acc(*adiv);
            C.ns1 = -softplus_acc(*a1) * LOG2E_F;
            C.ns2 = -softplus_acc(*a2) * LOG2E_F;
            C.ns3 = -softplus_acc(*a3) * LOG2E_F;
            C.ns4 = -softplus_acc(*a4) * LOG2E_F;
            float c1p = softplus_acc(*c1);
            float c2p = softplus_acc(*c2);
            float c3p = softplus_acc(*c3);
            float c4p = softplus_acc(*c4);
            float inv = KEHALF_F / (c1p + c2p + c3p + c4p);
            C.c1n = c1p * inv;
            C.c2n = c2p * inv;
            C.c3n = c3p * inv;
            C.c4n = c4p * inv;
            g_consts = C;
        }
    }
}

// Main pair kernel: 8 pairs per thread. Streamed loads use __ldcs (evict-first)
// to protect the byte table + output in L2. z recovered via a 32x-replicated
// smem LUT (bank == lane -> conflict-free).
__global__ void __launch_bounds__(256)
pair_kernel(const float4* __restrict__ rij, const float4* __restrict__ cut,
            const int4* __restrict__ ii, const int4* __restrict__ jj,
            float* __restrict__ out, int noct) {
    __shared__ float lutr[MAXZ * 32];
    int tid = threadIdx.x;
    int lane = tid & 31;
    for (int k = tid; k < MAXZ * 32; k += 256)
        lutr[k] = g_lut[k >> 5];
    ZConsts C = g_consts;
    __syncthreads();

    long long t = (long long)blockIdx.x * 256 + tid;  // index of 8-pair group
    if (t >= noct) return;

    float4 r0 = __ldcs(&rij[2 * t]);
    float4 r1 = __ldcs(&rij[2 * t + 1]);
    float4 v0 = __ldcs(&cut[2 * t]);
    float4 v1 = __ldcs(&cut[2 * t + 1]);
    int4 ia0 = __ldcs(&ii[2 * t]);
    int4 ia1 = __ldcs(&ii[2 * t + 1]);
    int4 ja0 = __ldcs(&jj[2 * t]);
    int4 ja1 = __ldcs(&jj[2 * t + 1]);

    float r[8]  = {r0.x, r0.y, r0.z, r0.w, r1.x, r1.y, r1.z, r1.w};
    float cv[8] = {v0.x, v0.y, v0.z, v0.w, v1.x, v1.y, v1.z, v1.w};
    int   ia[8] = {ia0.x, ia0.y, ia0.z, ia0.w, ia1.x, ia1.y, ia1.z, ia1.w};
    int   ja[8] = {ja0.x, ja0.y, ja0.z, ja0.w, ja1.x, ja1.y, ja1.z, ja1.w};

    // Batch all 16 byte-gathers first for MLP.
    unsigned int zi[8], zj[8];
#pragma unroll
    for (int k = 0; k < 8; k++) {
        zi[k] = g_zq[ia[k]];
        zj[k] = g_zq[ja[k]];
    }

#pragma unroll
    for (int k = 0; k < 8; k++) {
        float zpi = lutr[zi[k] * 32 + lane];
        float zpj = lutr[zj[k] * 32 + lane];
        float ar = (zpi + zpj) * C.spadiv * r[k];
        float f = C.c1n * exp2f(C.ns1 * ar)
                + C.c2n * exp2f(C.ns2 * ar)
                + C.c3n * exp2f(C.ns3 * ar)
                + C.c4n * exp2f(C.ns4 * ar);
        float zz = (float)(int)(zi[k] * zj[k]);
        float contrib = __fdividef(f * cv[k] * zz, r[k]);
        atomicAdd(out + ia[k], contrib);   // no return use -> RED
    }
}

// Scalar tail (P % 8 != 0); not hit for P = 16M but kept for generality.
__global__ void pair_tail(const float* __restrict__ rij, const float* __restrict__ cut,
                          const int* __restrict__ ii, const int* __restrict__ jj,
                          float* __restrict__ out, int start, int P) {
    int p = start + blockIdx.x * blockDim.x + threadIdx.x;
    if (p >= P) return;
    ZConsts C = g_consts;
    unsigned int qi = g_zq[ii[p]];
    unsigned int qj = g_zq[jj[p]];
    float zpi = g_lut[qi];
    float zpj = g_lut[qj];
    float ar = (zpi + zpj) * C.spadiv * rij[p];
    float f = C.c1n * exp2f(C.ns1 * ar)
            + C.c2n * exp2f(C.ns2 * ar)
            + C.c3n * exp2f(C.ns3 * ar)
            + C.c4n * exp2f(C.ns4 * ar);
    float zz = (float)(int)(qi * qj);
    float contrib = __fdividef(f * cut[p] * zz, rij[p]);
    atomicAdd(out + ii[p], contrib);
}

extern "C" void kernel_launch(void* const* d_in, const int* in_sizes, int n_in,
                              void* d_out, int out_size) {
    // order: N, Zf, rij, cutoff_values, idx_i, idx_j,
    //        adiv, apow, c1, c2, c3, c4, a1, a2, a3, a4
    const float* Zf   = (const float*)d_in[1];
    const float* rij  = (const float*)d_in[2];
    const float* cutv = (const float*)d_in[3];
    const int*   ii   = (const int*)d_in[4];
    const int*   jj   = (const int*)d_in[5];
    const float* adiv = (const float*)d_in[6];
    const float* apow = (const float*)d_in[7];
    const float* c1   = (const float*)d_in[8];
    const float* c2   = (const float*)d_in[9];
    const float* c3   = (const float*)d_in[10];
    const float* c4   = (const float*)d_in[11];
    const float* a1   = (const float*)d_in[12];
    const float* a2   = (const float*)d_in[13];
    const float* a3   = (const float*)d_in[14];
    const float* a4   = (const float*)d_in[15];
    float* out = (float*)d_out;

    int n_atoms = in_sizes[1];
    int P       = in_sizes[2];
    if (n_atoms > MAX_ATOMS) n_atoms = MAX_ATOMS;

    atom_kernel<<<(n_atoms + 255) / 256, 256>>>(Zf, out, n_atoms,
                                                adiv, apow, c1, c2, c3, c4,
                                                a1, a2, a3, a4);

    int noct = P / 8;
    if (noct > 0) {
        pair_kernel<<<(noct + 255) / 256, 256>>>(
            (const float4*)rij, (const float4*)cutv,
            (const int4*)ii, (const int4*)jj, out, noct);
    }
    int done = noct * 8;
    int rem = P - done;
    if (rem > 0) {
        pair_tail<<<(rem + 255) / 256, 256>>>(rij, cutv, ii, jj, out, done, P);
    }
}

// round 5
// speedup vs baseline: 1.1714x; 1.1714x over previous
#include <cuda_runtime.h>
#include <cuda_bf16.h>

#define KEHALF_F 7.199822675975274f
#define MAX_ATOMS 500000
#define MAXZ 96
#define LOG2E_F 1.4426950408889634f

struct ZConsts {
    float spadiv;               // sp(adiv)
    float ns1, ns2, ns3, ns4;   // -sp(a_k) * log2(e)
    float c1n, c2n, c3n, c4n;   // KEHALF * sp(c_k)/csum
};

__device__ ZConsts g_consts;
__device__ float g_lut[MAXZ];            // k^sp(apow); 384B, L1-resident
__device__ unsigned char g_zq[MAX_ATOMS];

__device__ __forceinline__ float softplus_acc(float x) {
    return (x > 20.f) ? x : log1pf(expf(x));
}

// Quantize Zf to bytes, zero the output; block 0 also computes the scalar
// constants and the 96-entry z LUT.
__global__ void __launch_bounds__(256)
atom_kernel(const float* __restrict__ Zf, float* __restrict__ out, int n,
            const float* adiv, const float* apow,
            const float* c1, const float* c2, const float* c3, const float* c4,
            const float* a1, const float* a2, const float* a3, const float* a4) {
    int i = blockIdx.x * blockDim.x + threadIdx.x;
    if (i < n) {
        g_zq[i] = (unsigned char)__float2int_rn(Zf[i]);
        out[i] = 0.0f;
    }
    if (blockIdx.x == 0) {
        if (threadIdx.x < MAXZ) {
            float sp_apow = softplus_acc(*apow);
            g_lut[threadIdx.x] = powf((float)threadIdx.x, sp_apow);
        }
        if (threadIdx.x == 0) {
            ZConsts C;
            C.spadiv = softplus_acc(*adiv);
            C.ns1 = -softplus_acc(*a1) * LOG2E_F;
            C.ns2 = -softplus_acc(*a2) * LOG2E_F;
            C.ns3 = -softplus_acc(*a3) * LOG2E_F;
            C.ns4 = -softplus_acc(*a4) * LOG2E_F;
            float c1p = softplus_acc(*c1);
            float c2p = softplus_acc(*c2);
            float c3p = softplus_acc(*c3);
            float c4p = softplus_acc(*c4);
            float inv = KEHALF_F / (c1p + c2p + c3p + c4p);
            C.c1n = c1p * inv;
            C.c2n = c2p * inv;
            C.c3n = c3p * inv;
            C.c4n = c4p * inv;
            g_consts = C;
        }
    }
}

// 8 pairs/thread. Zero smem (full L1D carveout for the 500KB byte table).
// z recovered from the 384B L1-resident float LUT. Streams are evict-first.
__global__ void __launch_bounds__(256)
pair_kernel(const float4* __restrict__ rij, const float4* __restrict__ cut,
            const int4* __restrict__ ii, const int4* __restrict__ jj,
            float* __restrict__ out, int noct) {
    long long t = (long long)blockIdx.x * 256 + threadIdx.x;  // 8-pair group
    if (t >= noct) return;
    ZConsts C = g_consts;

    float4 r0 = __ldcs(&rij[2 * t]);
    float4 r1 = __ldcs(&rij[2 * t + 1]);
    float4 v0 = __ldcs(&cut[2 * t]);
    float4 v1 = __ldcs(&cut[2 * t + 1]);
    int4 ia0 = __ldcs(&ii[2 * t]);
    int4 ia1 = __ldcs(&ii[2 * t + 1]);
    int4 ja0 = __ldcs(&jj[2 * t]);
    int4 ja1 = __ldcs(&jj[2 * t + 1]);

    float r[8]  = {r0.x, r0.y, r0.z, r0.w, r1.x, r1.y, r1.z, r1.w};
    float cv[8] = {v0.x, v0.y, v0.z, v0.w, v1.x, v1.y, v1.z, v1.w};
    int   ia[8] = {ia0.x, ia0.y, ia0.z, ia0.w, ia1.x, ia1.y, ia1.z, ia1.w};
    int   ja[8] = {ja0.x, ja0.y, ja0.z, ja0.w, ja1.x, ja1.y, ja1.z, ja1.w};

    // Batch all 16 random byte-gathers first for MLP.
    unsigned int zi[8], zj[8];
#pragma unroll
    for (int k = 0; k < 8; k++) {
        zi[k] = __ldg(&g_zq[ia[k]]);
        zj[k] = __ldg(&g_zq[ja[k]]);
    }

    // LUT lookups (L1-resident 384B table) — also batched.
    float zpi[8], zpj[8];
#pragma unroll
    for (int k = 0; k < 8; k++) {
        zpi[k] = __ldg(&g_lut[zi[k]]);
        zpj[k] = __ldg(&g_lut[zj[k]]);
    }

#pragma unroll
    for (int k = 0; k < 8; k++) {
        float ar = (zpi[k] + zpj[k]) * C.spadiv * r[k];
        float f = C.c1n * exp2f(C.ns1 * ar)
                + C.c2n * exp2f(C.ns2 * ar)
                + C.c3n * exp2f(C.ns3 * ar)
                + C.c4n * exp2f(C.ns4 * ar);
        float zz = (float)(int)(zi[k] * zj[k]);
        float contrib = __fdividef(f * cv[k] * zz, r[k]);
        atomicAdd(out + ia[k], contrib);   // unused return -> RED
    }
}

// Scalar tail (P % 8 != 0); not hit for P = 16M.
__global__ void pair_tail(const float* __restrict__ rij, const float* __restrict__ cut,
                          const int* __restrict__ ii, const int* __restrict__ jj,
                          float* __restrict__ out, int start, int P) {
    int p = start + blockIdx.x * blockDim.x + threadIdx.x;
    if (p >= P) return;
    ZConsts C = g_consts;
    unsigned int qi = g_zq[ii[p]];
    unsigned int qj = g_zq[jj[p]];
    float ar = (g_lut[qi] + g_lut[qj]) * C.spadiv * rij[p];
    float f = C.c1n * exp2f(C.ns1 * ar)
            + C.c2n * exp2f(C.ns2 * ar)
            + C.c3n * exp2f(C.ns3 * ar)
            + C.c4n * exp2f(C.ns4 * ar);
    float zz = (float)(int)(qi * qj);
    float contrib = __fdividef(f * cut[p] * zz, rij[p]);
    atomicAdd(out + ii[p], contrib);
}

extern "C" void kernel_launch(void* const* d_in, const int* in_sizes, int n_in,
                              void* d_out, int out_size) {
    // order: N, Zf, rij, cutoff_values, idx_i, idx_j,
    //        adiv, apow, c1, c2, c3, c4, a1, a2, a3, a4
    const float* Zf   = (const float*)d_in[1];
    const float* rij  = (const float*)d_in[2];
    const float* cutv = (const float*)d_in[3];
    const int*   ii   = (const int*)d_in[4];
    const int*   jj   = (const int*)d_in[5];
    const float* adiv = (const float*)d_in[6];
    const float* apow = (const float*)d_in[7];
    const float* c1   = (const float*)d_in[8];
    const float* c2   = (const float*)d_in[9];
    const float* c3   = (const float*)d_in[10];
    const float* c4   = (const float*)d_in[11];
    const float* a1   = (const float*)d_in[12];
    const float* a2   = (const float*)d_in[13];
    const float* a3   = (const float*)d_in[14];
    const float* a4   = (const float*)d_in[15];
    float* out = (float*)d_out;

    int n_atoms = in_sizes[1];
    int P       = in_sizes[2];
    if (n_atoms > MAX_ATOMS) n_atoms = MAX_ATOMS;

    atom_kernel<<<(n_atoms + 255) / 256, 256>>>(Zf, out, n_atoms,
                                                adiv, apow, c1, c2, c3, c4,
                                                a1, a2, a3, a4);

    int noct = P / 8;
    if (noct > 0) {
        pair_kernel<<<(noct + 255) / 256, 256>>>(
            (const float4*)rij, (const float4*)cutv,
            (const int4*)ii, (const int4*)jj, out, noct);
    }
    int done = noct * 8;
    int rem = P - done;
    if (rem > 0) {
        pair_tail<<<(rem + 255) / 256, 256>>>(rij, cutv, ii, jj, out, done, P);
    }
}